// round 2
// baseline (speedup 1.0000x reference)
#include <cuda_runtime.h>

#define NTOK  65536
#define NSLOT 4096
#define DDIM  768
#define LN_EPS 1e-5f

// Scratch for the LayerNorm'd activations (12.6 MB). Device global: allowed.
__device__ float g_normed[(size_t)NSLOT * DDIM];

__device__ __forceinline__ int lower_bound_dev(const int* __restrict__ a, int n, int key) {
    int lo = 0, hi = n;
    while (lo < hi) {
        int mid = (lo + hi) >> 1;
        if (__ldg(a + mid) < key) lo = mid + 1; else hi = mid;
    }
    return lo;
}

// One CTA per (b,s) slot. 192 threads, each owns one float4 lane of D=768.
__global__ void __launch_bounds__(192) embed_ln_kernel(
    const int*   __restrict__ token_ids,
    const int*   __restrict__ segment_ids,
    const int*   __restrict__ section_ids,
    const int*   __restrict__ temporality_ids,
    const int*   __restrict__ negation_ids,
    const int*   __restrict__ position_ids,
    const int*   __restrict__ timestamp_ids,
    const float* __restrict__ token_table,
    const float* __restrict__ section_table,
    const float* __restrict__ temporality_table,
    const float* __restrict__ negation_table,
    const float* __restrict__ position_table,
    const float* __restrict__ timestamp_table,
    const float* __restrict__ ln_gamma,
    const float* __restrict__ ln_beta)
{
    const int slot = blockIdx.x;
    const int tid  = threadIdx.x;   // 0..191

    // Segment range [lo, hi) for this slot (segment_ids is sorted).
    const int lo  = lower_bound_dev(segment_ids, NTOK, slot);
    const int hi  = lower_bound_dev(segment_ids, NTOK, slot + 1);
    const int cnt = hi - lo;

    float ax = 0.f, ay = 0.f, az = 0.f, aw = 0.f;
    float bx = 0.f, by = 0.f, bz = 0.f, bw = 0.f;

    int t = lo;
    for (; t + 2 <= hi; t += 2) {
        const int tok0 = __ldg(token_ids + t);
        const int tok1 = __ldg(token_ids + t + 1);
        const float4 v0 = __ldg((const float4*)(token_table + (size_t)tok0 * DDIM) + tid);
        const float4 v1 = __ldg((const float4*)(token_table + (size_t)tok1 * DDIM) + tid);
        ax += v0.x; ay += v0.y; az += v0.z; aw += v0.w;
        bx += v1.x; by += v1.y; bz += v1.z; bw += v1.w;
    }
    if (t < hi) {
        const int tok = __ldg(token_ids + t);
        const float4 v = __ldg((const float4*)(token_table + (size_t)tok * DDIM) + tid);
        ax += v.x; ay += v.y; az += v.z; aw += v.w;
    }
    ax += bx; ay += by; az += bz; aw += bw;

    const float inv = 1.0f / fmaxf((float)cnt, 1.0f);
    ax *= inv; ay *= inv; az *= inv; aw *= inv;

    // Multi-embedding sum (tables are tiny -> L1/L2 resident).
    {
        const int id = __ldg(section_ids + slot);
        const float4 v = __ldg((const float4*)(section_table + (size_t)id * DDIM) + tid);
        ax += v.x; ay += v.y; az += v.z; aw += v.w;
    }
    {
        const int id = __ldg(temporality_ids + slot);
        const float4 v = __ldg((const float4*)(temporality_table + (size_t)id * DDIM) + tid);
        ax += v.x; ay += v.y; az += v.z; aw += v.w;
    }
    {
        const int id = __ldg(negation_ids + slot);
        const float4 v = __ldg((const float4*)(negation_table + (size_t)id * DDIM) + tid);
        ax += v.x; ay += v.y; az += v.z; aw += v.w;
    }
    {
        const int id = __ldg(position_ids + slot);
        const float4 v = __ldg((const float4*)(position_table + (size_t)id * DDIM) + tid);
        ax += v.x; ay += v.y; az += v.z; aw += v.w;
    }
    {
        const int id = __ldg(timestamp_ids + slot);
        const float4 v = __ldg((const float4*)(timestamp_table + (size_t)id * DDIM) + tid);
        ax += v.x; ay += v.y; az += v.z; aw += v.w;
    }

    // LayerNorm reduction over 768 values (192 threads x 4).
    float s  = ax + ay + az + aw;
    float ss = ax * ax + ay * ay + az * az + aw * aw;

    #pragma unroll
    for (int o = 16; o > 0; o >>= 1) {
        s  += __shfl_down_sync(0xffffffffu, s,  o);
        ss += __shfl_down_sync(0xffffffffu, ss, o);
    }

    __shared__ float red_s[6];
    __shared__ float red_ss[6];
    __shared__ float stat[2];
    const int warp = tid >> 5;
    const int lane = tid & 31;
    if (lane == 0) { red_s[warp] = s; red_ss[warp] = ss; }
    __syncthreads();
    if (tid == 0) {
        float S = 0.f, SS = 0.f;
        #pragma unroll
        for (int i = 0; i < 6; i++) { S += red_s[i]; SS += red_ss[i]; }
        const float mean = S * (1.0f / DDIM);
        const float var  = SS * (1.0f / DDIM) - mean * mean;
        stat[0] = mean;
        stat[1] = rsqrtf(var + LN_EPS);
    }
    __syncthreads();
    const float mean = stat[0];
    const float rstd = stat[1];

    const float4 g = __ldg((const float4*)ln_gamma + tid);
    const float4 b = __ldg((const float4*)ln_beta  + tid);
    float4 o;
    o.x = (ax - mean) * rstd * g.x + b.x;
    o.y = (ay - mean) * rstd * g.y + b.y;
    o.z = (az - mean) * rstd * g.z + b.z;
    o.w = (aw - mean) * rstd * g.w + b.w;
    ((float4*)(g_normed + (size_t)slot * DDIM))[tid] = o;
}

// C[n][e] = sum_d A[n][d] * W[e][d] + bias[e]
// A = g_normed [4096, 768], W = proj_w [768, 768] (both K-major -> NT layout).
#define BM 128
#define BN 64
#define BK 16
#define TM 8
#define TN 4

__global__ void __launch_bounds__(256) gemm_kernel(
    const float* __restrict__ W,
    const float* __restrict__ bias,
    float*       __restrict__ C)
{
    __shared__ float As[BK][BM];
    __shared__ float Bs[BK][BN + 4];

    const int tid = threadIdx.x;
    const int bn  = blockIdx.x;    // 0..11
    const int bm  = blockIdx.y;    // 0..31
    const int tx  = tid & 15;      // n dir: 16 x TN(4) = 64
    const int ty  = tid >> 4;      // m dir: 16 x TM(8) = 128

    const float* A = g_normed;

    // A tile: 128 rows x 16 k. Each thread: 1 row, 8 consecutive floats.
    const int a_row = tid >> 1;
    const int a_kc  = (tid & 1) * 8;
    // W tile: 64 rows x 16 k. Each thread: 1 row, 4 consecutive floats.
    const int b_row = tid >> 2;
    const int b_kc  = (tid & 3) * 4;

    const float* a_ptr = A + (size_t)(bm * BM + a_row) * DDIM + a_kc;
    const float* b_ptr = W + (size_t)(bn * BN + b_row) * DDIM + b_kc;

    float acc[TM][TN];
    #pragma unroll
    for (int i = 0; i < TM; i++)
        #pragma unroll
        for (int j = 0; j < TN; j++) acc[i][j] = 0.f;

    for (int k0 = 0; k0 < DDIM; k0 += BK) {
        const float4 av0 = *(const float4*)(a_ptr + k0);
        const float4 av1 = *(const float4*)(a_ptr + k0 + 4);
        const float4 bv  = *(const float4*)(b_ptr + k0);

        As[a_kc + 0][a_row] = av0.x;
        As[a_kc + 1][a_row] = av0.y;
        As[a_kc + 2][a_row] = av0.z;
        As[a_kc + 3][a_row] = av0.w;
        As[a_kc + 4][a_row] = av1.x;
        As[a_kc + 5][a_row] = av1.y;
        As[a_kc + 6][a_row] = av1.z;
        As[a_kc + 7][a_row] = av1.w;

        Bs[b_kc + 0][b_row] = bv.x;
        Bs[b_kc + 1][b_row] = bv.y;
        Bs[b_kc + 2][b_row] = bv.z;
        Bs[b_kc + 3][b_row] = bv.w;
        __syncthreads();

        #pragma unroll
        for (int k = 0; k < BK; k++) {
            float a[TM], bb[TN];
            const float4 t0 = *(const float4*)&As[k][ty * TM];
            const float4 t1 = *(const float4*)&As[k][ty * TM + 4];
            a[0] = t0.x; a[1] = t0.y; a[2] = t0.z; a[3] = t0.w;
            a[4] = t1.x; a[5] = t1.y; a[6] = t1.z; a[7] = t1.w;
            const float4 tb = *(const float4*)&Bs[k][tx * TN];
            bb[0] = tb.x; bb[1] = tb.y; bb[2] = tb.z; bb[3] = tb.w;
            #pragma unroll
            for (int i = 0; i < TM; i++)
                #pragma unroll
                for (int j = 0; j < TN; j++)
                    acc[i][j] = fmaf(a[i], bb[j], acc[i][j]);
        }
        __syncthreads();
    }

    const float4 bv = __ldg((const float4*)(bias + bn * BN + tx * TN));
    #pragma unroll
    for (int i = 0; i < TM; i++) {
        const int row = bm * BM + ty * TM + i;
        float4 o;
        o.x = acc[i][0] + bv.x;
        o.y = acc[i][1] + bv.y;
        o.z = acc[i][2] + bv.z;
        o.w = acc[i][3] + bv.w;
        *(float4*)(C + (size_t)row * DDIM + bn * BN + tx * TN) = o;
    }
}

// Padding mask is all-false -> zero the tail of d_out past the tokens block.
__global__ void zero_tail_kernel(float* __restrict__ out, int start, int total) {
    const int i = start + blockIdx.x * blockDim.x + threadIdx.x;
    if (i < total) out[i] = 0.0f;
}

extern "C" void kernel_launch(void* const* d_in, const int* in_sizes, int n_in,
                              void* d_out, int out_size) {
    const int*   token_ids         = (const int*)  d_in[0];
    const int*   segment_ids       = (const int*)  d_in[1];
    const int*   section_ids       = (const int*)  d_in[2];
    const int*   temporality_ids   = (const int*)  d_in[3];
    const int*   negation_ids      = (const int*)  d_in[4];
    const int*   position_ids      = (const int*)  d_in[5];
    const int*   timestamp_ids     = (const int*)  d_in[6];
    const float* token_table       = (const float*)d_in[7];
    const float* section_table     = (const float*)d_in[8];
    const float* temporality_table = (const float*)d_in[9];
    const float* negation_table    = (const float*)d_in[10];
    const float* position_table    = (const float*)d_in[11];
    const float* timestamp_table   = (const float*)d_in[12];
    const float* ln_gamma          = (const float*)d_in[13];
    const float* ln_beta           = (const float*)d_in[14];
    const float* proj_w            = (const float*)d_in[15];
    const float* proj_b            = (const float*)d_in[16];

    float* out = (float*)d_out;

    embed_ln_kernel<<<NSLOT, 192>>>(
        token_ids, segment_ids, section_ids, temporality_ids, negation_ids,
        position_ids, timestamp_ids, token_table, section_table,
        temporality_table, negation_table, position_table, timestamp_table,
        ln_gamma, ln_beta);

    dim3 grid(DDIM / BN, NSLOT / BM);
    gemm_kernel<<<grid, 256>>>(proj_w, proj_b, out);

    const int ntok_out = NSLOT * DDIM;
    const int tail = out_size - ntok_out;
    if (tail > 0) {
        zero_tail_kernel<<<(tail + 255) / 256, 256>>>(out, ntok_out, out_size);
    }
}

// round 4
// speedup vs baseline: 2.1961x; 2.1961x over previous
#include <cuda_runtime.h>
#include <cuda_bf16.h>
#include <cstdint>

#define NTOK   65536
#define NSLOT  4096
#define DDIM   768
#define LN_EPS 1e-5f

// ---- tcgen05 capability gate (per device-compile pass) ----
#if (defined(__CUDA_ARCH_SPECIFIC__) && (__CUDA_ARCH_SPECIFIC__ >= 1000)) || \
    (defined(__CUDA_ARCH_FAMILY_SPECIFIC__) && (__CUDA_ARCH_FAMILY_SPECIFIC__ >= 1000)) || \
    defined(__CUDA_ARCH_FEAT_SM100_ALL) || defined(__CUDA_ARCH_FEAT_SM101_ALL) || \
    defined(__CUDA_ARCH_FEAT_SM103_ALL)
#define HAS_TCGEN05 1
#else
#define HAS_TCGEN05 0
#endif

// ---------------- device scratch (allowed: __device__ globals) ----------------
__device__ float         g_normed[(size_t)NSLOT * DDIM]; // fp32 LN output (SIMT path)
__device__ __nv_bfloat16 g_ahi[(size_t)NSLOT * DDIM];    // LN output, bf16 high part
__device__ __nv_bfloat16 g_alo[(size_t)NSLOT * DDIM];    // LN output, bf16 residual
__device__ __nv_bfloat16 g_whi[(size_t)DDIM * DDIM];     // proj_w high part
__device__ __nv_bfloat16 g_wlo[(size_t)DDIM * DDIM];     // proj_w residual

// ---------------- PTX helpers ----------------
__device__ __forceinline__ uint32_t smem_u32(const void* p) {
    uint32_t a;
    asm("{ .reg .u64 t; cvta.to.shared.u64 t, %1; cvt.u32.u64 %0, t; }" : "=r"(a) : "l"(p));
    return a;
}

#if HAS_TCGEN05

#define MBARRIER_INIT(addr, cnt) \
    asm volatile("mbarrier.init.shared.b64 [%0], %1;" :: "r"(addr), "r"(cnt) : "memory")

#define MBARRIER_WAIT_PARITY(mbar, parity) do {                                   \
    uint32_t _m = (mbar); uint32_t _p = (parity); uint32_t _done;                 \
    asm volatile("{\n .reg .pred p;\n"                                            \
        " mbarrier.try_wait.parity.acquire.cta.shared::cta.b64 p, [%1], %2;\n"    \
        " selp.b32 %0, 1, 0, p;\n}"                                               \
        : "=r"(_done) : "r"(_m), "r"(_p) : "memory");                             \
    if (!_done) {                                                                 \
        asm volatile("{\n .reg .pred P1;\n"                                       \
            "WL_%=:\n"                                                            \
            " mbarrier.try_wait.parity.acquire.cta.shared::cta.b64 P1, [%0], %1, 0x989680;\n" \
            " @P1 bra.uni WD_%=;\n bra.uni WL_%=;\nWD_%=:\n}"                     \
            :: "r"(_m), "r"(_p) : "memory");                                      \
    }                                                                             \
} while (0)

#define TCGEN05_ALLOC(smem_addr, ncols) \
    asm volatile("tcgen05.alloc.cta_group::1.sync.aligned.shared::cta.b32 [%0], %1;" \
                 :: "r"(smem_addr), "r"(ncols) : "memory")
#define TCGEN05_RELINQ() \
    asm volatile("tcgen05.relinquish_alloc_permit.cta_group::1.sync.aligned;")
#define TCGEN05_DEALLOC(tmem, ncols) \
    asm volatile("tcgen05.dealloc.cta_group::1.sync.aligned.b32 %0, %1;" :: "r"(tmem), "r"(ncols))
#define TCGEN05_COMMIT(mbar) \
    asm volatile("tcgen05.commit.cta_group::1.mbarrier::arrive::one.shared::cluster.b64 [%0];" \
                 :: "r"(mbar) : "memory")
#define TCGEN05_FENCE_AFTER() \
    asm volatile("tcgen05.fence::after_thread_sync;" ::: "memory")
#define TCGEN05_WAIT_LD() \
    asm volatile("tcgen05.wait::ld.sync.aligned;" ::: "memory")
#define FENCE_PROXY_ASYNC() \
    asm volatile("fence.proxy.async.shared::cta;" ::: "memory")

#define TCGEN05_LD_X32(r, tmem_addr)                                              \
    asm volatile("tcgen05.ld.sync.aligned.32x32b.x32.b32 "                        \
        "{%0, %1, %2, %3, %4, %5, %6, %7, "                                       \
        " %8, %9, %10, %11, %12, %13, %14, %15, "                                 \
        " %16, %17, %18, %19, %20, %21, %22, %23, "                               \
        " %24, %25, %26, %27, %28, %29, %30, %31}, [%32];"                        \
        : "=r"((r)[0]),  "=r"((r)[1]),  "=r"((r)[2]),  "=r"((r)[3]),              \
          "=r"((r)[4]),  "=r"((r)[5]),  "=r"((r)[6]),  "=r"((r)[7]),              \
          "=r"((r)[8]),  "=r"((r)[9]),  "=r"((r)[10]), "=r"((r)[11]),             \
          "=r"((r)[12]), "=r"((r)[13]), "=r"((r)[14]), "=r"((r)[15]),             \
          "=r"((r)[16]), "=r"((r)[17]), "=r"((r)[18]), "=r"((r)[19]),             \
          "=r"((r)[20]), "=r"((r)[21]), "=r"((r)[22]), "=r"((r)[23]),             \
          "=r"((r)[24]), "=r"((r)[25]), "=r"((r)[26]), "=r"((r)[27]),             \
          "=r"((r)[28]), "=r"((r)[29]), "=r"((r)[30]), "=r"((r)[31])              \
        : "r"(tmem_addr))

__device__ __forceinline__ void mma_bf16_ss(uint32_t d_tmem, uint64_t a_desc,
                                            uint64_t b_desc, uint32_t idesc,
                                            uint32_t enable_acc) {
    asm volatile("{\n .reg .pred p;\n setp.ne.u32 p, %5, 0;\n"
        " tcgen05.mma.cta_group::1.kind::f16 [%0], %1, %2, %3, {%4, %4, %4, %4}, p;\n}"
        :: "r"(d_tmem), "l"(a_desc), "l"(b_desc), "r"(idesc), "r"(0u), "r"(enable_acc)
        : "memory");
}

__device__ __forceinline__ uint64_t make_desc_sw128(uint32_t base_addr) {
    const uint64_t BASE = (uint64_t(2) << 61) | (uint64_t(1) << 46) |
                          (uint64_t(64) << 32) | (uint64_t(1) << 16);
    return BASE | ((uint64_t)(base_addr >> 4) & 0x3FFF);
}

#endif // HAS_TCGEN05

__device__ __forceinline__ void cp_async16(uint32_t dst, const __nv_bfloat16* src) {
    asm volatile("cp.async.cg.shared.global [%0], [%1], 16;"
                 :: "r"(dst), "l"(__cvta_generic_to_global(src)) : "memory");
}
#define CP_COMMIT() asm volatile("cp.async.commit_group;" ::: "memory")
#define CP_WAIT(n)  asm volatile("cp.async.wait_group %0;" :: "n"(n) : "memory")

__device__ __forceinline__ uint32_t sw128(uint32_t off) {
    return off ^ ((off >> 3) & 0x70);
}

// ======================= kernel 1: embed + pool + LN =======================
__device__ __forceinline__ int lower_bound_dev(const int* __restrict__ a, int n, int key) {
    int lo = 0, hi = n;
    while (lo < hi) {
        int mid = (lo + hi) >> 1;
        if (__ldg(a + mid) < key) lo = mid + 1; else hi = mid;
    }
    return lo;
}

__global__ void __launch_bounds__(192) embed_ln_kernel(
    const int*   __restrict__ token_ids,
    const int*   __restrict__ segment_ids,
    const int*   __restrict__ section_ids,
    const int*   __restrict__ temporality_ids,
    const int*   __restrict__ negation_ids,
    const int*   __restrict__ position_ids,
    const int*   __restrict__ timestamp_ids,
    const float* __restrict__ token_table,
    const float* __restrict__ section_table,
    const float* __restrict__ temporality_table,
    const float* __restrict__ negation_table,
    const float* __restrict__ position_table,
    const float* __restrict__ timestamp_table,
    const float* __restrict__ ln_gamma,
    const float* __restrict__ ln_beta)
{
    const int slot = blockIdx.x;
    const int tid  = threadIdx.x;   // 0..191

    const int lo  = lower_bound_dev(segment_ids, NTOK, slot);
    const int hi  = lower_bound_dev(segment_ids, NTOK, slot + 1);
    const int cnt = hi - lo;

    float4 a0 = {0.f,0.f,0.f,0.f}, a1 = {0.f,0.f,0.f,0.f};
    float4 a2 = {0.f,0.f,0.f,0.f}, a3 = {0.f,0.f,0.f,0.f};

    int t = lo;
    for (; t + 4 <= hi; t += 4) {
        const int t0 = __ldg(token_ids + t + 0);
        const int t1 = __ldg(token_ids + t + 1);
        const int t2 = __ldg(token_ids + t + 2);
        const int t3 = __ldg(token_ids + t + 3);
        const float4 v0 = __ldg((const float4*)(token_table + (size_t)t0 * DDIM) + tid);
        const float4 v1 = __ldg((const float4*)(token_table + (size_t)t1 * DDIM) + tid);
        const float4 v2 = __ldg((const float4*)(token_table + (size_t)t2 * DDIM) + tid);
        const float4 v3 = __ldg((const float4*)(token_table + (size_t)t3 * DDIM) + tid);
        a0.x += v0.x; a0.y += v0.y; a0.z += v0.z; a0.w += v0.w;
        a1.x += v1.x; a1.y += v1.y; a1.z += v1.z; a1.w += v1.w;
        a2.x += v2.x; a2.y += v2.y; a2.z += v2.z; a2.w += v2.w;
        a3.x += v3.x; a3.y += v3.y; a3.z += v3.z; a3.w += v3.w;
    }
    for (; t < hi; t++) {
        const int tok = __ldg(token_ids + t);
        const float4 v = __ldg((const float4*)(token_table + (size_t)tok * DDIM) + tid);
        a0.x += v.x; a0.y += v.y; a0.z += v.z; a0.w += v.w;
    }
    float ax = (a0.x + a1.x) + (a2.x + a3.x);
    float ay = (a0.y + a1.y) + (a2.y + a3.y);
    float az = (a0.z + a1.z) + (a2.z + a3.z);
    float aw = (a0.w + a1.w) + (a2.w + a3.w);

    const float inv = 1.0f / fmaxf((float)cnt, 1.0f);
    ax *= inv; ay *= inv; az *= inv; aw *= inv;

    {
        const int id = __ldg(section_ids + slot);
        const float4 v = __ldg((const float4*)(section_table + (size_t)id * DDIM) + tid);
        ax += v.x; ay += v.y; az += v.z; aw += v.w;
    }
    {
        const int id = __ldg(temporality_ids + slot);
        const float4 v = __ldg((const float4*)(temporality_table + (size_t)id * DDIM) + tid);
        ax += v.x; ay += v.y; az += v.z; aw += v.w;
    }
    {
        const int id = __ldg(negation_ids + slot);
        const float4 v = __ldg((const float4*)(negation_table + (size_t)id * DDIM) + tid);
        ax += v.x; ay += v.y; az += v.z; aw += v.w;
    }
    {
        const int id = __ldg(position_ids + slot);
        const float4 v = __ldg((const float4*)(position_table + (size_t)id * DDIM) + tid);
        ax += v.x; ay += v.y; az += v.z; aw += v.w;
    }
    {
        const int id = __ldg(timestamp_ids + slot);
        const float4 v = __ldg((const float4*)(timestamp_table + (size_t)id * DDIM) + tid);
        ax += v.x; ay += v.y; az += v.z; aw += v.w;
    }

    float s  = ax + ay + az + aw;
    float ss = ax * ax + ay * ay + az * az + aw * aw;
    #pragma unroll
    for (int o = 16; o > 0; o >>= 1) {
        s  += __shfl_down_sync(0xffffffffu, s,  o);
        ss += __shfl_down_sync(0xffffffffu, ss, o);
    }

    __shared__ float red_s[6], red_ss[6], stat[2];
    const int warp = tid >> 5, lane = tid & 31;
    if (lane == 0) { red_s[warp] = s; red_ss[warp] = ss; }
    __syncthreads();
    if (tid == 0) {
        float S = 0.f, SS = 0.f;
        #pragma unroll
        for (int i = 0; i < 6; i++) { S += red_s[i]; SS += red_ss[i]; }
        const float mean = S * (1.0f / DDIM);
        const float var  = SS * (1.0f / DDIM) - mean * mean;
        stat[0] = mean;
        stat[1] = rsqrtf(var + LN_EPS);
    }
    __syncthreads();
    const float mean = stat[0], rstd = stat[1];

    const float4 g = __ldg((const float4*)ln_gamma + tid);
    const float4 b = __ldg((const float4*)ln_beta  + tid);
    float ox = (ax - mean) * rstd * g.x + b.x;
    float oy = (ay - mean) * rstd * g.y + b.y;
    float oz = (az - mean) * rstd * g.z + b.z;
    float ow = (aw - mean) * rstd * g.w + b.w;

#if HAS_TCGEN05
    // bf16 hi/lo split for the tensor-core GEMM
    __nv_bfloat16 hx = __float2bfloat16_rn(ox), hy = __float2bfloat16_rn(oy);
    __nv_bfloat16 hz = __float2bfloat16_rn(oz), hw = __float2bfloat16_rn(ow);
    __nv_bfloat16 lx = __float2bfloat16_rn(ox - __bfloat162float(hx));
    __nv_bfloat16 ly = __float2bfloat16_rn(oy - __bfloat162float(hy));
    __nv_bfloat16 lz = __float2bfloat16_rn(oz - __bfloat162float(hz));
    __nv_bfloat16 lw = __float2bfloat16_rn(ow - __bfloat162float(hw));

    __nv_bfloat162* ph = (__nv_bfloat162*)(g_ahi + (size_t)slot * DDIM);
    __nv_bfloat162* pl = (__nv_bfloat162*)(g_alo + (size_t)slot * DDIM);
    ph[tid * 2 + 0] = __halves2bfloat162(hx, hy);
    ph[tid * 2 + 1] = __halves2bfloat162(hz, hw);
    pl[tid * 2 + 0] = __halves2bfloat162(lx, ly);
    pl[tid * 2 + 1] = __halves2bfloat162(lz, lw);
#else
    float4 o;
    o.x = ox; o.y = oy; o.z = oz; o.w = ow;
    ((float4*)(g_normed + (size_t)slot * DDIM))[tid] = o;
#endif
}

// ======================= kernel 2: split proj_w into bf16 hi/lo =======================
__global__ void __launch_bounds__(256) wsplit_kernel(const float* __restrict__ W) {
#if HAS_TCGEN05
    const int i = blockIdx.x * blockDim.x + threadIdx.x;   // per float4
    const float4 v = __ldg((const float4*)W + i);
    __nv_bfloat16 hx = __float2bfloat16_rn(v.x), hy = __float2bfloat16_rn(v.y);
    __nv_bfloat16 hz = __float2bfloat16_rn(v.z), hw = __float2bfloat16_rn(v.w);
    __nv_bfloat16 lx = __float2bfloat16_rn(v.x - __bfloat162float(hx));
    __nv_bfloat16 ly = __float2bfloat16_rn(v.y - __bfloat162float(hy));
    __nv_bfloat16 lz = __float2bfloat16_rn(v.z - __bfloat162float(hz));
    __nv_bfloat16 lw = __float2bfloat16_rn(v.w - __bfloat162float(hw));
    ((__nv_bfloat162*)g_whi)[i * 2 + 0] = __halves2bfloat162(hx, hy);
    ((__nv_bfloat162*)g_whi)[i * 2 + 1] = __halves2bfloat162(hz, hw);
    ((__nv_bfloat162*)g_wlo)[i * 2 + 0] = __halves2bfloat162(lx, ly);
    ((__nv_bfloat162*)g_wlo)[i * 2 + 1] = __halves2bfloat162(lz, lw);
#endif
}

// ======================= kernel 3a: tcgen05 bf16-split GEMM =======================
#define KCH     64
#define TILE_M  128
#define TILE_N  256
#define NCHUNK  (DDIM / KCH)          // 12

#define OFF_TM   0
#define OFF_MB   16
#define OFF_AH   1024
#define OFF_AL   (OFF_AH + 2*16384)
#define OFF_BH   (OFF_AL + 2*16384)
#define OFF_BL   (OFF_BH + 2*32768)
#define GEMM_SMEM (OFF_BL + 2*32768)   // 197632

__global__ void __launch_bounds__(256, 1) gemm_tc_kernel(
    const float* __restrict__ bias, float* __restrict__ C)
{
#if HAS_TCGEN05
    extern __shared__ char smem[];
    const uint32_t sb  = smem_u32(smem);
    const int tid = threadIdx.x;
    const int bn  = blockIdx.x;   // 0..2
    const int bm  = blockIdx.y;   // 0..31

    if (tid < 32) {
        TCGEN05_ALLOC(sb + OFF_TM, 256);
        TCGEN05_RELINQ();
    }
    if (tid == 0) {
        MBARRIER_INIT(sb + OFF_MB,     1);
        MBARRIER_INIT(sb + OFF_MB + 8, 1);
    }
    __syncthreads();
    uint32_t tmem;
    asm volatile("ld.shared.b32 %0, [%1];" : "=r"(tmem) : "r"(sb + OFF_TM));

    uint32_t a_dst[4];
    const __nv_bfloat16 *a_srch[4], *a_srcl[4];
    #pragma unroll
    for (int j = 0; j < 4; j++) {
        const int ci  = tid + j * 256;
        const int row = ci >> 3, c16 = ci & 7;
        a_dst[j]  = sw128((uint32_t)(row * 128 + c16 * 16));
        const size_t e = (size_t)(bm * TILE_M + row) * DDIM + c16 * 8;
        a_srch[j] = g_ahi + e;
        a_srcl[j] = g_alo + e;
    }
    uint32_t b_dst[8];
    const __nv_bfloat16 *b_srch[8], *b_srcl[8];
    #pragma unroll
    for (int j = 0; j < 8; j++) {
        const int ci  = tid + j * 256;
        const int row = ci >> 3, c16 = ci & 7;
        b_dst[j]  = sw128((uint32_t)(row * 128 + c16 * 16));
        const size_t e = (size_t)(bn * TILE_N + row) * DDIM + c16 * 8;
        b_srch[j] = g_whi + e;
        b_srcl[j] = g_wlo + e;
    }

    auto load_chunk = [&](int c, int buf) {
        const uint32_t ah = sb + OFF_AH + buf * 16384;
        const uint32_t al = sb + OFF_AL + buf * 16384;
        const uint32_t bh = sb + OFF_BH + buf * 32768;
        const uint32_t bl = sb + OFF_BL + buf * 32768;
        const int koff = c * KCH;
        #pragma unroll
        for (int j = 0; j < 4; j++) {
            cp_async16(ah + a_dst[j], a_srch[j] + koff);
            cp_async16(al + a_dst[j], a_srcl[j] + koff);
        }
        #pragma unroll
        for (int j = 0; j < 8; j++) {
            cp_async16(bh + b_dst[j], b_srch[j] + koff);
            cp_async16(bl + b_dst[j], b_srcl[j] + koff);
        }
        CP_COMMIT();
    };

    load_chunk(0, 0);
    load_chunk(1, 1);

    const uint32_t idesc = (1u << 4) | (1u << 7) | (1u << 10) |
                           ((TILE_N / 8) << 17) | ((TILE_M / 16) << 24);

    for (int c = 0; c < NCHUNK; c++) {
        const int buf = c & 1;
        CP_WAIT(1);
        FENCE_PROXY_ASYNC();
        __syncthreads();

        if (tid == 0) {
            const uint64_t dAH = make_desc_sw128(sb + OFF_AH + buf * 16384);
            const uint64_t dAL = make_desc_sw128(sb + OFF_AL + buf * 16384);
            const uint64_t dBH = make_desc_sw128(sb + OFF_BH + buf * 32768);
            const uint64_t dBL = make_desc_sw128(sb + OFF_BL + buf * 32768);
            #pragma unroll
            for (int ks = 0; ks < 4; ks++) {
                const uint64_t o = ks * 2;
                mma_bf16_ss(tmem, dAH + o, dBH + o, idesc, (c | ks) != 0);
                mma_bf16_ss(tmem, dAH + o, dBL + o, idesc, 1u);
                mma_bf16_ss(tmem, dAL + o, dBH + o, idesc, 1u);
            }
            TCGEN05_COMMIT(sb + OFF_MB + buf * 8);
        }
        MBARRIER_WAIT_PARITY(sb + OFF_MB + buf * 8, (uint32_t)((c >> 1) & 1));

        if (c + 2 < NCHUNK) load_chunk(c + 2, buf);
    }

    TCGEN05_FENCE_AFTER();

    const int w    = tid >> 5, lane = tid & 31;
    const int part = w & 3,    half = w >> 2;
    const int row  = bm * TILE_M + part * 32 + lane;
    float* crow = C + (size_t)row * DDIM;

    #pragma unroll
    for (int batch = 0; batch < 4; batch++) {
        const int colbase = half * 128 + batch * 32;
        uint32_t r[32];
        TCGEN05_LD_X32(r, tmem + colbase);
        TCGEN05_WAIT_LD();
        const int gcol0 = bn * TILE_N + colbase;
        #pragma unroll
        for (int i = 0; i < 32; i += 4) {
            const float4 bv = __ldg((const float4*)(bias + gcol0 + i));
            float4 o;
            o.x = __uint_as_float(r[i + 0]) + bv.x;
            o.y = __uint_as_float(r[i + 1]) + bv.y;
            o.z = __uint_as_float(r[i + 2]) + bv.z;
            o.w = __uint_as_float(r[i + 3]) + bv.w;
            *(float4*)(crow + gcol0 + i) = o;
        }
    }

    __syncthreads();
    if (tid < 32) TCGEN05_DEALLOC(tmem, 256);
#endif // HAS_TCGEN05
}

// ======================= kernel 3b: SIMT FP32 GEMM fallback =======================
#define BM 128
#define BN 64
#define BK 16
#define TM 8
#define TN 4

__global__ void __launch_bounds__(256) gemm_simt_kernel(
    const float* __restrict__ W,
    const float* __restrict__ bias,
    float*       __restrict__ C)
{
#if !HAS_TCGEN05
    __shared__ float As[BK][BM];
    __shared__ float Bs[BK][BN + 4];

    const int tid = threadIdx.x;
    const int bn  = blockIdx.x;
    const int bm  = blockIdx.y;
    const int tx  = tid & 15;
    const int ty  = tid >> 4;

    const float* A = g_normed;

    const int a_row = tid >> 1;
    const int a_kc  = (tid & 1) * 8;
    const int b_row = tid >> 2;
    const int b_kc  = (tid & 3) * 4;

    const float* a_ptr = A + (size_t)(bm * BM + a_row) * DDIM + a_kc;
    const float* b_ptr = W + (size_t)(bn * BN + b_row) * DDIM + b_kc;

    float acc[TM][TN];
    #pragma unroll
    for (int i = 0; i < TM; i++)
        #pragma unroll
        for (int j = 0; j < TN; j++) acc[i][j] = 0.f;

    for (int k0 = 0; k0 < DDIM; k0 += BK) {
        const float4 av0 = *(const float4*)(a_ptr + k0);
        const float4 av1 = *(const float4*)(a_ptr + k0 + 4);
        const float4 bv  = *(const float4*)(b_ptr + k0);

        As[a_kc + 0][a_row] = av0.x;
        As[a_kc + 1][a_row] = av0.y;
        As[a_kc + 2][a_row] = av0.z;
        As[a_kc + 3][a_row] = av0.w;
        As[a_kc + 4][a_row] = av1.x;
        As[a_kc + 5][a_row] = av1.y;
        As[a_kc + 6][a_row] = av1.z;
        As[a_kc + 7][a_row] = av1.w;

        Bs[b_kc + 0][b_row] = bv.x;
        Bs[b_kc + 1][b_row] = bv.y;
        Bs[b_kc + 2][b_row] = bv.z;
        Bs[b_kc + 3][b_row] = bv.w;
        __syncthreads();

        #pragma unroll
        for (int k = 0; k < BK; k++) {
            float a[TM], bb[TN];
            const float4 t0 = *(const float4*)&As[k][ty * TM];
            const float4 t1 = *(const float4*)&As[k][ty * TM + 4];
            a[0] = t0.x; a[1] = t0.y; a[2] = t0.z; a[3] = t0.w;
            a[4] = t1.x; a[5] = t1.y; a[6] = t1.z; a[7] = t1.w;
            const float4 tb = *(const float4*)&Bs[k][tx * TN];
            bb[0] = tb.x; bb[1] = tb.y; bb[2] = tb.z; bb[3] = tb.w;
            #pragma unroll
            for (int i = 0; i < TM; i++)
                #pragma unroll
                for (int j = 0; j < TN; j++)
                    acc[i][j] = fmaf(a[i], bb[j], acc[i][j]);
        }
        __syncthreads();
    }

    const float4 bv = __ldg((const float4*)(bias + bn * BN + tx * TN));
    #pragma unroll
    for (int i = 0; i < TM; i++) {
        const int row = bm * BM + ty * TM + i;
        float4 o;
        o.x = acc[i][0] + bv.x;
        o.y = acc[i][1] + bv.y;
        o.z = acc[i][2] + bv.z;
        o.w = acc[i][3] + bv.w;
        *(float4*)(C + (size_t)row * DDIM + bn * BN + tx * TN) = o;
    }
#endif // !HAS_TCGEN05
}

// ======================= kernel 4: zero the mask tail =======================
__global__ void zero_tail_kernel(float* __restrict__ out, int start, int total) {
    const int i = start + blockIdx.x * blockDim.x + threadIdx.x;
    if (i < total) out[i] = 0.0f;
}

// ======================= launch =======================
extern "C" void kernel_launch(void* const* d_in, const int* in_sizes, int n_in,
                              void* d_out, int out_size) {
    const int*   token_ids         = (const int*)  d_in[0];
    const int*   segment_ids       = (const int*)  d_in[1];
    const int*   section_ids       = (const int*)  d_in[2];
    const int*   temporality_ids   = (const int*)  d_in[3];
    const int*   negation_ids      = (const int*)  d_in[4];
    const int*   position_ids      = (const int*)  d_in[5];
    const int*   timestamp_ids     = (const int*)  d_in[6];
    const float* token_table       = (const float*)d_in[7];
    const float* section_table     = (const float*)d_in[8];
    const float* temporality_table = (const float*)d_in[9];
    const float* negation_table    = (const float*)d_in[10];
    const float* position_table    = (const float*)d_in[11];
    const float* timestamp_table   = (const float*)d_in[12];
    const float* ln_gamma          = (const float*)d_in[13];
    const float* ln_beta           = (const float*)d_in[14];
    const float* proj_w            = (const float*)d_in[15];
    const float* proj_b            = (const float*)d_in[16];

    float* out = (float*)d_out;

    cudaFuncSetAttribute(gemm_tc_kernel,
                         cudaFuncAttributeMaxDynamicSharedMemorySize, GEMM_SMEM);

    wsplit_kernel<<<(DDIM * DDIM / 4) / 256, 256>>>(proj_w);

    embed_ln_kernel<<<NSLOT, 192>>>(
        token_ids, segment_ids, section_ids, temporality_ids, negation_ids,
        position_ids, timestamp_ids, token_table, section_table,
        temporality_table, negation_table, position_table, timestamp_table,
        ln_gamma, ln_beta);

    // Exactly one of these two does work, selected per-arch at compile time.
    dim3 grid_tc(DDIM / TILE_N, NSLOT / TILE_M);   // (3, 32)
    gemm_tc_kernel<<<grid_tc, 256, GEMM_SMEM>>>(proj_b, out);

    dim3 grid_simt(DDIM / BN, NSLOT / BM);         // (12, 32)
    gemm_simt_kernel<<<grid_simt, 256>>>(proj_w, proj_b, out);

    const int ntok_out = NSLOT * DDIM;
    const int tail = out_size - ntok_out;
    if (tail > 0) {
        zero_tail_kernel<<<(tail + 255) / 256, 256>>>(out, ntok_out, out_size);
    }
}

// round 5
// speedup vs baseline: 2.8985x; 1.3198x over previous
#include <cuda_runtime.h>
#include <cuda_bf16.h>
#include <cstdint>

#define NTOK   65536
#define NSLOT  4096
#define DDIM   768
#define LN_EPS 1e-5f

// ---- tcgen05 capability gate (per device-compile pass) ----
#if (defined(__CUDA_ARCH_SPECIFIC__) && (__CUDA_ARCH_SPECIFIC__ >= 1000)) || \
    (defined(__CUDA_ARCH_FAMILY_SPECIFIC__) && (__CUDA_ARCH_FAMILY_SPECIFIC__ >= 1000)) || \
    defined(__CUDA_ARCH_FEAT_SM100_ALL) || defined(__CUDA_ARCH_FEAT_SM101_ALL) || \
    defined(__CUDA_ARCH_FEAT_SM103_ALL)
#define HAS_TCGEN05 1
#else
#define HAS_TCGEN05 0
#endif

// ---------------- device scratch ----------------
__device__ __nv_bfloat16 g_ahi[(size_t)NSLOT * DDIM];    // LN output, bf16 high part
__device__ __nv_bfloat16 g_alo[(size_t)NSLOT * DDIM];    // LN output, bf16 residual
__device__ __nv_bfloat16 g_whi[(size_t)DDIM * DDIM];     // proj_w high part
__device__ __nv_bfloat16 g_wlo[(size_t)DDIM * DDIM];     // proj_w residual
__device__ int           g_segstart[NSLOT + 1];          // token range starts

// ---------------- PTX helpers ----------------
__device__ __forceinline__ uint32_t smem_u32(const void* p) {
    uint32_t a;
    asm("{ .reg .u64 t; cvta.to.shared.u64 t, %1; cvt.u32.u64 %0, t; }" : "=r"(a) : "l"(p));
    return a;
}

#if HAS_TCGEN05

#define MBARRIER_INIT(addr, cnt) \
    asm volatile("mbarrier.init.shared.b64 [%0], %1;" :: "r"(addr), "r"(cnt) : "memory")

#define MBARRIER_WAIT_PARITY(mbar, parity) do {                                   \
    uint32_t _m = (mbar); uint32_t _p = (parity); uint32_t _done;                 \
    asm volatile("{\n .reg .pred p;\n"                                            \
        " mbarrier.try_wait.parity.acquire.cta.shared::cta.b64 p, [%1], %2;\n"    \
        " selp.b32 %0, 1, 0, p;\n}"                                               \
        : "=r"(_done) : "r"(_m), "r"(_p) : "memory");                             \
    if (!_done) {                                                                 \
        asm volatile("{\n .reg .pred P1;\n"                                       \
            "WL_%=:\n"                                                            \
            " mbarrier.try_wait.parity.acquire.cta.shared::cta.b64 P1, [%0], %1, 0x989680;\n" \
            " @P1 bra.uni WD_%=;\n bra.uni WL_%=;\nWD_%=:\n}"                     \
            :: "r"(_m), "r"(_p) : "memory");                                      \
    }                                                                             \
} while (0)

#define TCGEN05_ALLOC(smem_addr, ncols) \
    asm volatile("tcgen05.alloc.cta_group::1.sync.aligned.shared::cta.b32 [%0], %1;" \
                 :: "r"(smem_addr), "r"(ncols) : "memory")
#define TCGEN05_RELINQ() \
    asm volatile("tcgen05.relinquish_alloc_permit.cta_group::1.sync.aligned;")
#define TCGEN05_DEALLOC(tmem, ncols) \
    asm volatile("tcgen05.dealloc.cta_group::1.sync.aligned.b32 %0, %1;" :: "r"(tmem), "r"(ncols))
#define TCGEN05_COMMIT(mbar) \
    asm volatile("tcgen05.commit.cta_group::1.mbarrier::arrive::one.shared::cluster.b64 [%0];" \
                 :: "r"(mbar) : "memory")
#define TCGEN05_FENCE_AFTER() \
    asm volatile("tcgen05.fence::after_thread_sync;" ::: "memory")
#define TCGEN05_WAIT_LD() \
    asm volatile("tcgen05.wait::ld.sync.aligned;" ::: "memory")
#define FENCE_PROXY_ASYNC() \
    asm volatile("fence.proxy.async.shared::cta;" ::: "memory")

#define TCGEN05_LD_X32(r, tmem_addr)                                              \
    asm volatile("tcgen05.ld.sync.aligned.32x32b.x32.b32 "                        \
        "{%0, %1, %2, %3, %4, %5, %6, %7, "                                       \
        " %8, %9, %10, %11, %12, %13, %14, %15, "                                 \
        " %16, %17, %18, %19, %20, %21, %22, %23, "                               \
        " %24, %25, %26, %27, %28, %29, %30, %31}, [%32];"                        \
        : "=r"((r)[0]),  "=r"((r)[1]),  "=r"((r)[2]),  "=r"((r)[3]),              \
          "=r"((r)[4]),  "=r"((r)[5]),  "=r"((r)[6]),  "=r"((r)[7]),              \
          "=r"((r)[8]),  "=r"((r)[9]),  "=r"((r)[10]), "=r"((r)[11]),             \
          "=r"((r)[12]), "=r"((r)[13]), "=r"((r)[14]), "=r"((r)[15]),             \
          "=r"((r)[16]), "=r"((r)[17]), "=r"((r)[18]), "=r"((r)[19]),             \
          "=r"((r)[20]), "=r"((r)[21]), "=r"((r)[22]), "=r"((r)[23]),             \
          "=r"((r)[24]), "=r"((r)[25]), "=r"((r)[26]), "=r"((r)[27]),             \
          "=r"((r)[28]), "=r"((r)[29]), "=r"((r)[30]), "=r"((r)[31])              \
        : "r"(tmem_addr))

__device__ __forceinline__ void mma_bf16_ss(uint32_t d_tmem, uint64_t a_desc,
                                            uint64_t b_desc, uint32_t idesc,
                                            uint32_t enable_acc) {
    asm volatile("{\n .reg .pred p;\n setp.ne.u32 p, %5, 0;\n"
        " tcgen05.mma.cta_group::1.kind::f16 [%0], %1, %2, %3, {%4, %4, %4, %4}, p;\n}"
        :: "r"(d_tmem), "l"(a_desc), "l"(b_desc), "r"(idesc), "r"(0u), "r"(enable_acc)
        : "memory");
}

__device__ __forceinline__ uint64_t make_desc_sw128(uint32_t base_addr) {
    const uint64_t BASE = (uint64_t(2) << 61) | (uint64_t(1) << 46) |
                          (uint64_t(64) << 32) | (uint64_t(1) << 16);
    return BASE | ((uint64_t)(base_addr >> 4) & 0x3FFF);
}

#endif // HAS_TCGEN05

__device__ __forceinline__ void cp_async16(uint32_t dst, const __nv_bfloat16* src) {
    asm volatile("cp.async.cg.shared.global [%0], [%1], 16;"
                 :: "r"(dst), "l"(__cvta_generic_to_global(src)) : "memory");
}
#define CP_COMMIT() asm volatile("cp.async.commit_group;" ::: "memory")
#define CP_WAIT(n)  asm volatile("cp.async.wait_group %0;" :: "n"(n) : "memory")

__device__ __forceinline__ uint32_t sw128(uint32_t off) {
    return off ^ ((off >> 3) & 0x70);
}

// ======================= kernel 0: segment starts =======================
// g_segstart[slot] = first t with segment_ids[t] >= slot  (segment_ids sorted)
__global__ void __launch_bounds__(256) segstart_kernel(const int* __restrict__ segment_ids) {
    const int t = blockIdx.x * blockDim.x + threadIdx.x;
    if (t >= NTOK) return;
    const int cur = __ldg(segment_ids + t);
    if (t == 0) {
        for (int s = 0; s <= cur; s++) g_segstart[s] = 0;
    } else {
        const int prev = __ldg(segment_ids + t - 1);
        for (int s = prev + 1; s <= cur; s++) g_segstart[s] = t;
    }
    if (t == NTOK - 1) {
        for (int s = cur + 1; s <= NSLOT; s++) g_segstart[s] = NTOK;
    }
}

// ======================= kernel 1: embed + pool + LN =======================
__global__ void __launch_bounds__(192) embed_ln_kernel(
    const int*   __restrict__ token_ids,
    const int*   __restrict__ section_ids,
    const int*   __restrict__ temporality_ids,
    const int*   __restrict__ negation_ids,
    const int*   __restrict__ position_ids,
    const int*   __restrict__ timestamp_ids,
    const float* __restrict__ token_table,
    const float* __restrict__ section_table,
    const float* __restrict__ temporality_table,
    const float* __restrict__ negation_table,
    const float* __restrict__ position_table,
    const float* __restrict__ timestamp_table,
    const float* __restrict__ ln_gamma,
    const float* __restrict__ ln_beta)
{
    const int slot = blockIdx.x;
    const int tid  = threadIdx.x;   // 0..191

    const int lo  = __ldg(g_segstart + slot);
    const int hi  = __ldg(g_segstart + slot + 1);
    const int cnt = hi - lo;

    float4 a0 = {0.f,0.f,0.f,0.f}, a1 = {0.f,0.f,0.f,0.f};
    float4 a2 = {0.f,0.f,0.f,0.f}, a3 = {0.f,0.f,0.f,0.f};

    int t = lo;
    // 8-deep gather for MLP; accumulate into 4 accumulators.
    for (; t + 8 <= hi; t += 8) {
        int tk[8];
        #pragma unroll
        for (int j = 0; j < 8; j++) tk[j] = __ldg(token_ids + t + j);
        float4 v[8];
        #pragma unroll
        for (int j = 0; j < 8; j++)
            v[j] = __ldg((const float4*)(token_table + (size_t)tk[j] * DDIM) + tid);
        a0.x += v[0].x + v[4].x; a0.y += v[0].y + v[4].y; a0.z += v[0].z + v[4].z; a0.w += v[0].w + v[4].w;
        a1.x += v[1].x + v[5].x; a1.y += v[1].y + v[5].y; a1.z += v[1].z + v[5].z; a1.w += v[1].w + v[5].w;
        a2.x += v[2].x + v[6].x; a2.y += v[2].y + v[6].y; a2.z += v[2].z + v[6].z; a2.w += v[2].w + v[6].w;
        a3.x += v[3].x + v[7].x; a3.y += v[3].y + v[7].y; a3.z += v[3].z + v[7].z; a3.w += v[3].w + v[7].w;
    }
    for (; t + 4 <= hi; t += 4) {
        int tk[4];
        #pragma unroll
        for (int j = 0; j < 4; j++) tk[j] = __ldg(token_ids + t + j);
        float4 v[4];
        #pragma unroll
        for (int j = 0; j < 4; j++)
            v[j] = __ldg((const float4*)(token_table + (size_t)tk[j] * DDIM) + tid);
        a0.x += v[0].x; a0.y += v[0].y; a0.z += v[0].z; a0.w += v[0].w;
        a1.x += v[1].x; a1.y += v[1].y; a1.z += v[1].z; a1.w += v[1].w;
        a2.x += v[2].x; a2.y += v[2].y; a2.z += v[2].z; a2.w += v[2].w;
        a3.x += v[3].x; a3.y += v[3].y; a3.z += v[3].z; a3.w += v[3].w;
    }
    for (; t < hi; t++) {
        const int tok = __ldg(token_ids + t);
        const float4 v = __ldg((const float4*)(token_table + (size_t)tok * DDIM) + tid);
        a0.x += v.x; a0.y += v.y; a0.z += v.z; a0.w += v.w;
    }
    float ax = (a0.x + a1.x) + (a2.x + a3.x);
    float ay = (a0.y + a1.y) + (a2.y + a3.y);
    float az = (a0.z + a1.z) + (a2.z + a3.z);
    float aw = (a0.w + a1.w) + (a2.w + a3.w);

    const float inv = 1.0f / fmaxf((float)cnt, 1.0f);
    ax *= inv; ay *= inv; az *= inv; aw *= inv;

    {
        const int id = __ldg(section_ids + slot);
        const float4 v = __ldg((const float4*)(section_table + (size_t)id * DDIM) + tid);
        ax += v.x; ay += v.y; az += v.z; aw += v.w;
    }
    {
        const int id = __ldg(temporality_ids + slot);
        const float4 v = __ldg((const float4*)(temporality_table + (size_t)id * DDIM) + tid);
        ax += v.x; ay += v.y; az += v.z; aw += v.w;
    }
    {
        const int id = __ldg(negation_ids + slot);
        const float4 v = __ldg((const float4*)(negation_table + (size_t)id * DDIM) + tid);
        ax += v.x; ay += v.y; az += v.z; aw += v.w;
    }
    {
        const int id = __ldg(position_ids + slot);
        const float4 v = __ldg((const float4*)(position_table + (size_t)id * DDIM) + tid);
        ax += v.x; ay += v.y; az += v.z; aw += v.w;
    }
    {
        const int id = __ldg(timestamp_ids + slot);
        const float4 v = __ldg((const float4*)(timestamp_table + (size_t)id * DDIM) + tid);
        ax += v.x; ay += v.y; az += v.z; aw += v.w;
    }

    float s  = ax + ay + az + aw;
    float ss = ax * ax + ay * ay + az * az + aw * aw;
    #pragma unroll
    for (int o = 16; o > 0; o >>= 1) {
        s  += __shfl_down_sync(0xffffffffu, s,  o);
        ss += __shfl_down_sync(0xffffffffu, ss, o);
    }

    __shared__ float red_s[6], red_ss[6], stat[2];
    const int warp = tid >> 5, lane = tid & 31;
    if (lane == 0) { red_s[warp] = s; red_ss[warp] = ss; }
    __syncthreads();
    if (tid == 0) {
        float S = 0.f, SS = 0.f;
        #pragma unroll
        for (int i = 0; i < 6; i++) { S += red_s[i]; SS += red_ss[i]; }
        const float mean = S * (1.0f / DDIM);
        const float var  = SS * (1.0f / DDIM) - mean * mean;
        stat[0] = mean;
        stat[1] = rsqrtf(var + LN_EPS);
    }
    __syncthreads();
    const float mean = stat[0], rstd = stat[1];

    const float4 g = __ldg((const float4*)ln_gamma + tid);
    const float4 b = __ldg((const float4*)ln_beta  + tid);
    float ox = (ax - mean) * rstd * g.x + b.x;
    float oy = (ay - mean) * rstd * g.y + b.y;
    float oz = (az - mean) * rstd * g.z + b.z;
    float ow = (aw - mean) * rstd * g.w + b.w;

    // bf16 hi/lo split for the tensor-core GEMM
    __nv_bfloat16 hx = __float2bfloat16_rn(ox), hy = __float2bfloat16_rn(oy);
    __nv_bfloat16 hz = __float2bfloat16_rn(oz), hw = __float2bfloat16_rn(ow);
    __nv_bfloat16 lx = __float2bfloat16_rn(ox - __bfloat162float(hx));
    __nv_bfloat16 ly = __float2bfloat16_rn(oy - __bfloat162float(hy));
    __nv_bfloat16 lz = __float2bfloat16_rn(oz - __bfloat162float(hz));
    __nv_bfloat16 lw = __float2bfloat16_rn(ow - __bfloat162float(hw));

    __nv_bfloat162* ph = (__nv_bfloat162*)(g_ahi + (size_t)slot * DDIM);
    __nv_bfloat162* pl = (__nv_bfloat162*)(g_alo + (size_t)slot * DDIM);
    ph[tid * 2 + 0] = __halves2bfloat162(hx, hy);
    ph[tid * 2 + 1] = __halves2bfloat162(hz, hw);
    pl[tid * 2 + 0] = __halves2bfloat162(lx, ly);
    pl[tid * 2 + 1] = __halves2bfloat162(lz, lw);
}

// ======================= kernel 2: split proj_w into bf16 hi/lo =======================
__global__ void __launch_bounds__(256) wsplit_kernel(const float* __restrict__ W) {
    const int i = blockIdx.x * blockDim.x + threadIdx.x;   // per float4
    const float4 v = __ldg((const float4*)W + i);
    __nv_bfloat16 hx = __float2bfloat16_rn(v.x), hy = __float2bfloat16_rn(v.y);
    __nv_bfloat16 hz = __float2bfloat16_rn(v.z), hw = __float2bfloat16_rn(v.w);
    __nv_bfloat16 lx = __float2bfloat16_rn(v.x - __bfloat162float(hx));
    __nv_bfloat16 ly = __float2bfloat16_rn(v.y - __bfloat162float(hy));
    __nv_bfloat16 lz = __float2bfloat16_rn(v.z - __bfloat162float(hz));
    __nv_bfloat16 lw = __float2bfloat16_rn(v.w - __bfloat162float(hw));
    ((__nv_bfloat162*)g_whi)[i * 2 + 0] = __halves2bfloat162(hx, hy);
    ((__nv_bfloat162*)g_whi)[i * 2 + 1] = __halves2bfloat162(hz, hw);
    ((__nv_bfloat162*)g_wlo)[i * 2 + 0] = __halves2bfloat162(lx, ly);
    ((__nv_bfloat162*)g_wlo)[i * 2 + 1] = __halves2bfloat162(lz, lw);
}

// ======================= kernel 3: tcgen05 bf16-split GEMM =======================
#define KCH     64
#define TILE_M  128
#define TILE_N  256
#define NCHUNK  (DDIM / KCH)          // 12

#define OFF_TM   0
#define OFF_MB   16
#define OFF_AH   1024
#define OFF_AL   (OFF_AH + 2*16384)
#define OFF_BH   (OFF_AL + 2*16384)
#define OFF_BL   (OFF_BH + 2*32768)
#define GEMM_SMEM (OFF_BL + 2*32768)   // 197632

__global__ void __launch_bounds__(256, 1) gemm_tc_kernel(
    const float* __restrict__ bias, float* __restrict__ C,
    int tail_start, int total_out)
{
#if HAS_TCGEN05
    extern __shared__ char smem[];
    const uint32_t sb  = smem_u32(smem);
    const int tid = threadIdx.x;
    const int bn  = blockIdx.x;   // 0..2
    const int bm  = blockIdx.y;   // 0..31

    // CTA (0,0) also zeros the mask tail of the output.
    if (bn == 0 && bm == 0) {
        for (int i = tail_start + tid; i < total_out; i += 256) C[i] = 0.0f;
    }

    if (tid < 32) {
        TCGEN05_ALLOC(sb + OFF_TM, 256);
        TCGEN05_RELINQ();
    }
    if (tid == 0) {
        MBARRIER_INIT(sb + OFF_MB,     1);
        MBARRIER_INIT(sb + OFF_MB + 8, 1);
    }
    __syncthreads();
    uint32_t tmem;
    asm volatile("ld.shared.b32 %0, [%1];" : "=r"(tmem) : "r"(sb + OFF_TM));

    uint32_t a_dst[4];
    const __nv_bfloat16 *a_srch[4], *a_srcl[4];
    #pragma unroll
    for (int j = 0; j < 4; j++) {
        const int ci  = tid + j * 256;
        const int row = ci >> 3, c16 = ci & 7;
        a_dst[j]  = sw128((uint32_t)(row * 128 + c16 * 16));
        const size_t e = (size_t)(bm * TILE_M + row) * DDIM + c16 * 8;
        a_srch[j] = g_ahi + e;
        a_srcl[j] = g_alo + e;
    }
    uint32_t b_dst[8];
    const __nv_bfloat16 *b_srch[8], *b_srcl[8];
    #pragma unroll
    for (int j = 0; j < 8; j++) {
        const int ci  = tid + j * 256;
        const int row = ci >> 3, c16 = ci & 7;
        b_dst[j]  = sw128((uint32_t)(row * 128 + c16 * 16));
        const size_t e = (size_t)(bn * TILE_N + row) * DDIM + c16 * 8;
        b_srch[j] = g_whi + e;
        b_srcl[j] = g_wlo + e;
    }

    auto load_chunk = [&](int c, int buf) {
        const uint32_t ah = sb + OFF_AH + buf * 16384;
        const uint32_t al = sb + OFF_AL + buf * 16384;
        const uint32_t bh = sb + OFF_BH + buf * 32768;
        const uint32_t bl = sb + OFF_BL + buf * 32768;
        const int koff = c * KCH;
        #pragma unroll
        for (int j = 0; j < 4; j++) {
            cp_async16(ah + a_dst[j], a_srch[j] + koff);
            cp_async16(al + a_dst[j], a_srcl[j] + koff);
        }
        #pragma unroll
        for (int j = 0; j < 8; j++) {
            cp_async16(bh + b_dst[j], b_srch[j] + koff);
            cp_async16(bl + b_dst[j], b_srcl[j] + koff);
        }
        CP_COMMIT();
    };

    load_chunk(0, 0);
    load_chunk(1, 1);

    const uint32_t idesc = (1u << 4) | (1u << 7) | (1u << 10) |
                           ((TILE_N / 8) << 17) | ((TILE_M / 16) << 24);

    for (int c = 0; c < NCHUNK; c++) {
        const int buf = c & 1;
        CP_WAIT(1);
        FENCE_PROXY_ASYNC();
        __syncthreads();

        if (tid == 0) {
            const uint64_t dAH = make_desc_sw128(sb + OFF_AH + buf * 16384);
            const uint64_t dAL = make_desc_sw128(sb + OFF_AL + buf * 16384);
            const uint64_t dBH = make_desc_sw128(sb + OFF_BH + buf * 32768);
            const uint64_t dBL = make_desc_sw128(sb + OFF_BL + buf * 32768);
            #pragma unroll
            for (int ks = 0; ks < 4; ks++) {
                const uint64_t o = ks * 2;
                mma_bf16_ss(tmem, dAH + o, dBH + o, idesc, (c | ks) != 0);
                mma_bf16_ss(tmem, dAH + o, dBL + o, idesc, 1u);
                mma_bf16_ss(tmem, dAL + o, dBH + o, idesc, 1u);
            }
            TCGEN05_COMMIT(sb + OFF_MB + buf * 8);
        }
        MBARRIER_WAIT_PARITY(sb + OFF_MB + buf * 8, (uint32_t)((c >> 1) & 1));

        if (c + 2 < NCHUNK) load_chunk(c + 2, buf);
    }

    TCGEN05_FENCE_AFTER();

    const int w    = tid >> 5, lane = tid & 31;
    const int part = w & 3,    half = w >> 2;
    const int row  = bm * TILE_M + part * 32 + lane;
    float* crow = C + (size_t)row * DDIM;

    #pragma unroll
    for (int batch = 0; batch < 4; batch++) {
        const int colbase = half * 128 + batch * 32;
        uint32_t r[32];
        TCGEN05_LD_X32(r, tmem + colbase);
        TCGEN05_WAIT_LD();
        const int gcol0 = bn * TILE_N + colbase;
        #pragma unroll
        for (int i = 0; i < 32; i += 4) {
            const float4 bv = __ldg((const float4*)(bias + gcol0 + i));
            float4 o;
            o.x = __uint_as_float(r[i + 0]) + bv.x;
            o.y = __uint_as_float(r[i + 1]) + bv.y;
            o.z = __uint_as_float(r[i + 2]) + bv.z;
            o.w = __uint_as_float(r[i + 3]) + bv.w;
            *(float4*)(crow + gcol0 + i) = o;
        }
    }

    __syncthreads();
    if (tid < 32) TCGEN05_DEALLOC(tmem, 256);
#endif // HAS_TCGEN05
}

// ======================= launch =======================
extern "C" void kernel_launch(void* const* d_in, const int* in_sizes, int n_in,
                              void* d_out, int out_size) {
    const int*   token_ids         = (const int*)  d_in[0];
    const int*   segment_ids       = (const int*)  d_in[1];
    const int*   section_ids       = (const int*)  d_in[2];
    const int*   temporality_ids   = (const int*)  d_in[3];
    const int*   negation_ids      = (const int*)  d_in[4];
    const int*   position_ids      = (const int*)  d_in[5];
    const int*   timestamp_ids     = (const int*)  d_in[6];
    const float* token_table       = (const float*)d_in[7];
    const float* section_table     = (const float*)d_in[8];
    const float* temporality_table = (const float*)d_in[9];
    const float* negation_table    = (const float*)d_in[10];
    const float* position_table    = (const float*)d_in[11];
    const float* timestamp_table   = (const float*)d_in[12];
    const float* ln_gamma          = (const float*)d_in[13];
    const float* ln_beta           = (const float*)d_in[14];
    const float* proj_w            = (const float*)d_in[15];
    const float* proj_b            = (const float*)d_in[16];

    float* out = (float*)d_out;

    cudaFuncSetAttribute(gemm_tc_kernel,
                         cudaFuncAttributeMaxDynamicSharedMemorySize, GEMM_SMEM);

    segstart_kernel<<<NTOK / 256, 256>>>(segment_ids);

    wsplit_kernel<<<(DDIM * DDIM / 4) / 256, 256>>>(proj_w);

    embed_ln_kernel<<<NSLOT, 192>>>(
        token_ids, section_ids, temporality_ids, negation_ids,
        position_ids, timestamp_ids, token_table, section_table,
        temporality_table, negation_table, position_table, timestamp_table,
        ln_gamma, ln_beta);

    dim3 grid_tc(DDIM / TILE_N, NSLOT / TILE_M);   // (3, 32)
    gemm_tc_kernel<<<grid_tc, 256, GEMM_SMEM>>>(proj_b, out,
                                                NSLOT * DDIM, out_size);
}

// round 9
// speedup vs baseline: 3.0064x; 1.0372x over previous
#include <cuda_runtime.h>
#include <cuda_bf16.h>
#include <cstdint>

#define NTOK   65536
#define NSLOT  4096
#define DDIM   768
#define LN_EPS 1e-5f

// ---- tcgen05 capability gate (per device-compile pass) ----
#if (defined(__CUDA_ARCH_SPECIFIC__) && (__CUDA_ARCH_SPECIFIC__ >= 1000)) || \
    (defined(__CUDA_ARCH_FAMILY_SPECIFIC__) && (__CUDA_ARCH_FAMILY_SPECIFIC__ >= 1000)) || \
    defined(__CUDA_ARCH_FEAT_SM100_ALL) || defined(__CUDA_ARCH_FEAT_SM101_ALL) || \
    defined(__CUDA_ARCH_FEAT_SM103_ALL)
#define HAS_TCGEN05 1
#else
#define HAS_TCGEN05 0
#endif

// ---------------- device scratch ----------------
__device__ __nv_bfloat16 g_ahi[(size_t)NSLOT * DDIM];    // LN output, bf16 high part
__device__ __nv_bfloat16 g_alo[(size_t)NSLOT * DDIM];    // LN output, bf16 residual
__device__ __nv_bfloat16 g_whi[(size_t)DDIM * DDIM];     // proj_w high part
__device__ __nv_bfloat16 g_wlo[(size_t)DDIM * DDIM];     // proj_w residual
__device__ int           g_segstart[NSLOT + 1];          // token range starts

// ---------------- PTX helpers ----------------
__device__ __forceinline__ uint32_t smem_u32(const void* p) {
    uint32_t a;
    asm("{ .reg .u64 t; cvta.to.shared.u64 t, %1; cvt.u32.u64 %0, t; }" : "=r"(a) : "l"(p));
    return a;
}

#if HAS_TCGEN05

#define MBARRIER_INIT(addr, cnt) \
    asm volatile("mbarrier.init.shared.b64 [%0], %1;" :: "r"(addr), "r"(cnt) : "memory")

#define MBARRIER_WAIT_PARITY(mbar, parity) do {                                   \
    uint32_t _m = (mbar); uint32_t _p = (parity); uint32_t _done;                 \
    asm volatile("{\n .reg .pred p;\n"                                            \
        " mbarrier.try_wait.parity.acquire.cta.shared::cta.b64 p, [%1], %2;\n"    \
        " selp.b32 %0, 1, 0, p;\n}"                                               \
        : "=r"(_done) : "r"(_m), "r"(_p) : "memory");                             \
    if (!_done) {                                                                 \
        asm volatile("{\n .reg .pred P1;\n"                                       \
            "WL_%=:\n"                                                            \
            " mbarrier.try_wait.parity.acquire.cta.shared::cta.b64 P1, [%0], %1, 0x989680;\n" \
            " @P1 bra.uni WD_%=;\n bra.uni WL_%=;\nWD_%=:\n}"                     \
            :: "r"(_m), "r"(_p) : "memory");                                      \
    }                                                                             \
} while (0)

#define TCGEN05_ALLOC(smem_addr, ncols) \
    asm volatile("tcgen05.alloc.cta_group::1.sync.aligned.shared::cta.b32 [%0], %1;" \
                 :: "r"(smem_addr), "r"(ncols) : "memory")
#define TCGEN05_RELINQ() \
    asm volatile("tcgen05.relinquish_alloc_permit.cta_group::1.sync.aligned;")
#define TCGEN05_DEALLOC(tmem, ncols) \
    asm volatile("tcgen05.dealloc.cta_group::1.sync.aligned.b32 %0, %1;" :: "r"(tmem), "r"(ncols))
#define TCGEN05_COMMIT(mbar) \
    asm volatile("tcgen05.commit.cta_group::1.mbarrier::arrive::one.shared::cluster.b64 [%0];" \
                 :: "r"(mbar) : "memory")
#define TCGEN05_FENCE_AFTER() \
    asm volatile("tcgen05.fence::after_thread_sync;" ::: "memory")
#define TCGEN05_WAIT_LD() \
    asm volatile("tcgen05.wait::ld.sync.aligned;" ::: "memory")
#define FENCE_PROXY_ASYNC() \
    asm volatile("fence.proxy.async.shared::cta;" ::: "memory")

#define TCGEN05_LD_X32(r, tmem_addr)                                              \
    asm volatile("tcgen05.ld.sync.aligned.32x32b.x32.b32 "                        \
        "{%0, %1, %2, %3, %4, %5, %6, %7, "                                       \
        " %8, %9, %10, %11, %12, %13, %14, %15, "                                 \
        " %16, %17, %18, %19, %20, %21, %22, %23, "                               \
        " %24, %25, %26, %27, %28, %29, %30, %31}, [%32];"                        \
        : "=r"((r)[0]),  "=r"((r)[1]),  "=r"((r)[2]),  "=r"((r)[3]),              \
          "=r"((r)[4]),  "=r"((r)[5]),  "=r"((r)[6]),  "=r"((r)[7]),              \
          "=r"((r)[8]),  "=r"((r)[9]),  "=r"((r)[10]), "=r"((r)[11]),             \
          "=r"((r)[12]), "=r"((r)[13]), "=r"((r)[14]), "=r"((r)[15]),             \
          "=r"((r)[16]), "=r"((r)[17]), "=r"((r)[18]), "=r"((r)[19]),             \
          "=r"((r)[20]), "=r"((r)[21]), "=r"((r)[22]), "=r"((r)[23]),             \
          "=r"((r)[24]), "=r"((r)[25]), "=r"((r)[26]), "=r"((r)[27]),             \
          "=r"((r)[28]), "=r"((r)[29]), "=r"((r)[30]), "=r"((r)[31])              \
        : "r"(tmem_addr))

__device__ __forceinline__ void mma_bf16_ss(uint32_t d_tmem, uint64_t a_desc,
                                            uint64_t b_desc, uint32_t idesc,
                                            uint32_t enable_acc) {
    asm volatile("{\n .reg .pred p;\n setp.ne.u32 p, %5, 0;\n"
        " tcgen05.mma.cta_group::1.kind::f16 [%0], %1, %2, %3, {%4, %4, %4, %4}, p;\n}"
        :: "r"(d_tmem), "l"(a_desc), "l"(b_desc), "r"(idesc), "r"(0u), "r"(enable_acc)
        : "memory");
}

// SW64 K-major descriptor: layout=4, version=1, SBO=32 (512B = 8 rows x 64B), LBO=1
__device__ __forceinline__ uint64_t make_desc_sw64(uint32_t base_addr) {
    const uint64_t BASE = (uint64_t(4) << 61) | (uint64_t(1) << 46) |
                          (uint64_t(32) << 32) | (uint64_t(1) << 16);
    return BASE | ((uint64_t)(base_addr >> 4) & 0x3FFF);
}

#endif // HAS_TCGEN05

__device__ __forceinline__ void cp_async16(uint32_t dst, const __nv_bfloat16* src) {
    asm volatile("cp.async.cg.shared.global [%0], [%1], 16;"
                 :: "r"(dst), "l"(__cvta_generic_to_global(src)) : "memory");
}
#define CP_COMMIT() asm volatile("cp.async.commit_group;" ::: "memory")
#define CP_WAIT(n)  asm volatile("cp.async.wait_group %0;" :: "n"(n) : "memory")

__device__ __forceinline__ uint32_t sw64(uint32_t off) {
    return off ^ ((off >> 3) & 0x30);
}

// ======================= kernel 0: segment starts =======================
__global__ void __launch_bounds__(256) segstart_kernel(const int* __restrict__ segment_ids) {
    const int t = blockIdx.x * blockDim.x + threadIdx.x;
    if (t >= NTOK) return;
    const int cur = __ldg(segment_ids + t);
    if (t == 0) {
        for (int s = 0; s <= cur; s++) g_segstart[s] = 0;
    } else {
        const int prev = __ldg(segment_ids + t - 1);
        for (int s = prev + 1; s <= cur; s++) g_segstart[s] = t;
    }
    if (t == NTOK - 1) {
        for (int s = cur + 1; s <= NSLOT; s++) g_segstart[s] = NTOK;
    }
}

// ======================= kernel 1: embed + pool + LN =======================
__global__ void __launch_bounds__(192) embed_ln_kernel(
    const int*   __restrict__ token_ids,
    const int*   __restrict__ section_ids,
    const int*   __restrict__ temporality_ids,
    const int*   __restrict__ negation_ids,
    const int*   __restrict__ position_ids,
    const int*   __restrict__ timestamp_ids,
    const float* __restrict__ token_table,
    const float* __restrict__ section_table,
    const float* __restrict__ temporality_table,
    const float* __restrict__ negation_table,
    const float* __restrict__ position_table,
    const float* __restrict__ timestamp_table,
    const float* __restrict__ ln_gamma,
    const float* __restrict__ ln_beta)
{
    const int slot = blockIdx.x;
    const int tid  = threadIdx.x;   // 0..191

    const int lo  = __ldg(g_segstart + slot);
    const int hi  = __ldg(g_segstart + slot + 1);
    const int cnt = hi - lo;

    float4 a0 = {0.f,0.f,0.f,0.f}, a1 = {0.f,0.f,0.f,0.f};
    float4 a2 = {0.f,0.f,0.f,0.f}, a3 = {0.f,0.f,0.f,0.f};

    int t = lo;
    for (; t + 8 <= hi; t += 8) {
        int tk[8];
        #pragma unroll
        for (int j = 0; j < 8; j++) tk[j] = __ldg(token_ids + t + j);
        float4 v[8];
        #pragma unroll
        for (int j = 0; j < 8; j++)
            v[j] = __ldg((const float4*)(token_table + (size_t)tk[j] * DDIM) + tid);
        a0.x += v[0].x + v[4].x; a0.y += v[0].y + v[4].y; a0.z += v[0].z + v[4].z; a0.w += v[0].w + v[4].w;
        a1.x += v[1].x + v[5].x; a1.y += v[1].y + v[5].y; a1.z += v[1].z + v[5].z; a1.w += v[1].w + v[5].w;
        a2.x += v[2].x + v[6].x; a2.y += v[2].y + v[6].y; a2.z += v[2].z + v[6].z; a2.w += v[2].w + v[6].w;
        a3.x += v[3].x + v[7].x; a3.y += v[3].y + v[7].y; a3.z += v[3].z + v[7].z; a3.w += v[3].w + v[7].w;
    }
    for (; t + 4 <= hi; t += 4) {
        int tk[4];
        #pragma unroll
        for (int j = 0; j < 4; j++) tk[j] = __ldg(token_ids + t + j);
        float4 v[4];
        #pragma unroll
        for (int j = 0; j < 4; j++)
            v[j] = __ldg((const float4*)(token_table + (size_t)tk[j] * DDIM) + tid);
        a0.x += v[0].x; a0.y += v[0].y; a0.z += v[0].z; a0.w += v[0].w;
        a1.x += v[1].x; a1.y += v[1].y; a1.z += v[1].z; a1.w += v[1].w;
        a2.x += v[2].x; a2.y += v[2].y; a2.z += v[2].z; a2.w += v[2].w;
        a3.x += v[3].x; a3.y += v[3].y; a3.z += v[3].z; a3.w += v[3].w;
    }
    for (; t < hi; t++) {
        const int tok = __ldg(token_ids + t);
        const float4 v = __ldg((const float4*)(token_table + (size_t)tok * DDIM) + tid);
        a0.x += v.x; a0.y += v.y; a0.z += v.z; a0.w += v.w;
    }
    float ax = (a0.x + a1.x) + (a2.x + a3.x);
    float ay = (a0.y + a1.y) + (a2.y + a3.y);
    float az = (a0.z + a1.z) + (a2.z + a3.z);
    float aw = (a0.w + a1.w) + (a2.w + a3.w);

    const float inv = 1.0f / fmaxf((float)cnt, 1.0f);
    ax *= inv; ay *= inv; az *= inv; aw *= inv;

    {
        const int id = __ldg(section_ids + slot);
        const float4 v = __ldg((const float4*)(section_table + (size_t)id * DDIM) + tid);
        ax += v.x; ay += v.y; az += v.z; aw += v.w;
    }
    {
        const int id = __ldg(temporality_ids + slot);
        const float4 v = __ldg((const float4*)(temporality_table + (size_t)id * DDIM) + tid);
        ax += v.x; ay += v.y; az += v.z; aw += v.w;
    }
    {
        const int id = __ldg(negation_ids + slot);
        const float4 v = __ldg((const float4*)(negation_table + (size_t)id * DDIM) + tid);
        ax += v.x; ay += v.y; az += v.z; aw += v.w;
    }
    {
        const int id = __ldg(position_ids + slot);
        const float4 v = __ldg((const float4*)(position_table + (size_t)id * DDIM) + tid);
        ax += v.x; ay += v.y; az += v.z; aw += v.w;
    }
    {
        const int id = __ldg(timestamp_ids + slot);
        const float4 v = __ldg((const float4*)(timestamp_table + (size_t)id * DDIM) + tid);
        ax += v.x; ay += v.y; az += v.z; aw += v.w;
    }

    float s  = ax + ay + az + aw;
    float ss = ax * ax + ay * ay + az * az + aw * aw;
    #pragma unroll
    for (int o = 16; o > 0; o >>= 1) {
        s  += __shfl_down_sync(0xffffffffu, s,  o);
        ss += __shfl_down_sync(0xffffffffu, ss, o);
    }

    __shared__ float red_s[6], red_ss[6], stat[2];
    const int warp = tid >> 5, lane = tid & 31;
    if (lane == 0) { red_s[warp] = s; red_ss[warp] = ss; }
    __syncthreads();
    if (tid == 0) {
        float S = 0.f, SS = 0.f;
        #pragma unroll
        for (int i = 0; i < 6; i++) { S += red_s[i]; SS += red_ss[i]; }
        const float mean = S * (1.0f / DDIM);
        const float var  = SS * (1.0f / DDIM) - mean * mean;
        stat[0] = mean;
        stat[1] = rsqrtf(var + LN_EPS);
    }
    __syncthreads();
    const float mean = stat[0], rstd = stat[1];

    const float4 g = __ldg((const float4*)ln_gamma + tid);
    const float4 b = __ldg((const float4*)ln_beta  + tid);
    float ox = (ax - mean) * rstd * g.x + b.x;
    float oy = (ay - mean) * rstd * g.y + b.y;
    float oz = (az - mean) * rstd * g.z + b.z;
    float ow = (aw - mean) * rstd * g.w + b.w;

    __nv_bfloat16 hx = __float2bfloat16_rn(ox), hy = __float2bfloat16_rn(oy);
    __nv_bfloat16 hz = __float2bfloat16_rn(oz), hw = __float2bfloat16_rn(ow);
    __nv_bfloat16 lx = __float2bfloat16_rn(ox - __bfloat162float(hx));
    __nv_bfloat16 ly = __float2bfloat16_rn(oy - __bfloat162float(hy));
    __nv_bfloat16 lz = __float2bfloat16_rn(oz - __bfloat162float(hz));
    __nv_bfloat16 lw = __float2bfloat16_rn(ow - __bfloat162float(hw));

    __nv_bfloat162* ph = (__nv_bfloat162*)(g_ahi + (size_t)slot * DDIM);
    __nv_bfloat162* pl = (__nv_bfloat162*)(g_alo + (size_t)slot * DDIM);
    ph[tid * 2 + 0] = __halves2bfloat162(hx, hy);
    ph[tid * 2 + 1] = __halves2bfloat162(hz, hw);
    pl[tid * 2 + 0] = __halves2bfloat162(lx, ly);
    pl[tid * 2 + 1] = __halves2bfloat162(lz, lw);
}

// ======================= kernel 2: split proj_w into bf16 hi/lo =======================
__global__ void __launch_bounds__(256) wsplit_kernel(const float* __restrict__ W) {
    const int i = blockIdx.x * blockDim.x + threadIdx.x;   // per float4
    const float4 v = __ldg((const float4*)W + i);
    __nv_bfloat16 hx = __float2bfloat16_rn(v.x), hy = __float2bfloat16_rn(v.y);
    __nv_bfloat16 hz = __float2bfloat16_rn(v.z), hw = __float2bfloat16_rn(v.w);
    __nv_bfloat16 lx = __float2bfloat16_rn(v.x - __bfloat162float(hx));
    __nv_bfloat16 ly = __float2bfloat16_rn(v.y - __bfloat162float(hy));
    __nv_bfloat16 lz = __float2bfloat16_rn(v.z - __bfloat162float(hz));
    __nv_bfloat16 lw = __float2bfloat16_rn(v.w - __bfloat162float(hw));
    ((__nv_bfloat162*)g_whi)[i * 2 + 0] = __halves2bfloat162(hx, hy);
    ((__nv_bfloat162*)g_whi)[i * 2 + 1] = __halves2bfloat162(hz, hw);
    ((__nv_bfloat162*)g_wlo)[i * 2 + 0] = __halves2bfloat162(lx, ly);
    ((__nv_bfloat162*)g_wlo)[i * 2 + 1] = __halves2bfloat162(lz, lw);
}

// ======================= kernel 3: tcgen05 bf16-split GEMM =======================
// 4-stage pipeline, K-chunks of 32 bf16 (64B rows, SW64 swizzle).
#define KCH     32
#define TILE_M  128
#define TILE_N  256
#define NCHUNK  (DDIM / KCH)           // 24
#define NBUF    4

#define SZ_A    (TILE_M * 64)          // 8192 bytes per matrix per chunk
#define SZ_B    (TILE_N * 64)          // 16384
#define SZ_BUF  (2*SZ_A + 2*SZ_B)      // 49152

#define OFF_TM   0
#define OFF_MB   16                    // 4 mbarriers @ +0,+8,+16,+24
#define OFF_DATA 1024
// within a buffer: AH @0, AL @SZ_A, BH @2*SZ_A, BL @2*SZ_A+SZ_B
#define GEMM_SMEM (OFF_DATA + NBUF*SZ_BUF)   // 197632

__global__ void __launch_bounds__(256, 1) gemm_tc_kernel(
    const float* __restrict__ bias, float* __restrict__ C,
    int tail_start, int total_out)
{
#if HAS_TCGEN05
    extern __shared__ char smem[];
    const uint32_t sb  = smem_u32(smem);
    const int tid = threadIdx.x;
    const int bn  = blockIdx.x;   // 0..2
    const int bm  = blockIdx.y;   // 0..31

    if (bn == 0 && bm == 0) {
        for (int i = tail_start + tid; i < total_out; i += 256) C[i] = 0.0f;
    }

    if (tid < 32) {
        TCGEN05_ALLOC(sb + OFF_TM, 256);
        TCGEN05_RELINQ();
    }
    if (tid == 0) {
        #pragma unroll
        for (int i = 0; i < NBUF; i++) MBARRIER_INIT(sb + OFF_MB + i * 8, 1);
    }
    __syncthreads();
    uint32_t tmem;
    asm volatile("ld.shared.b32 %0, [%1];" : "=r"(tmem) : "r"(sb + OFF_TM));

    // -------- per-thread load geometry (64B rows) --------
    // A: 128 rows x 4 16B-chunks = 512; 2 per thread (per hi/lo).
    uint32_t a_dst[2];
    const __nv_bfloat16 *a_srch[2], *a_srcl[2];
    #pragma unroll
    for (int j = 0; j < 2; j++) {
        const int ci  = tid + j * 256;
        const int row = ci >> 2, c16 = ci & 3;
        a_dst[j]  = sw64((uint32_t)(row * 64 + c16 * 16));
        const size_t e = (size_t)(bm * TILE_M + row) * DDIM + c16 * 8;
        a_srch[j] = g_ahi + e;
        a_srcl[j] = g_alo + e;
    }
    // B: 256 rows x 4 = 1024; 4 per thread (per hi/lo).
    uint32_t b_dst[4];
    const __nv_bfloat16 *b_srch[4], *b_srcl[4];
    #pragma unroll
    for (int j = 0; j < 4; j++) {
        const int ci  = tid + j * 256;
        const int row = ci >> 2, c16 = ci & 3;
        b_dst[j]  = sw64((uint32_t)(row * 64 + c16 * 16));
        const size_t e = (size_t)(bn * TILE_N + row) * DDIM + c16 * 8;
        b_srch[j] = g_whi + e;
        b_srcl[j] = g_wlo + e;
    }

    auto load_chunk = [&](int c) {
        const int buf = c & (NBUF - 1);
        const uint32_t base = sb + OFF_DATA + buf * SZ_BUF;
        const uint32_t ah = base;
        const uint32_t al = base + SZ_A;
        const uint32_t bh = base + 2 * SZ_A;
        const uint32_t bl = base + 2 * SZ_A + SZ_B;
        const int koff = c * KCH;
        #pragma unroll
        for (int j = 0; j < 2; j++) {
            cp_async16(ah + a_dst[j], a_srch[j] + koff);
            cp_async16(al + a_dst[j], a_srcl[j] + koff);
        }
        #pragma unroll
        for (int j = 0; j < 4; j++) {
            cp_async16(bh + b_dst[j], b_srch[j] + koff);
            cp_async16(bl + b_dst[j], b_srcl[j] + koff);
        }
        CP_COMMIT();
    };

    load_chunk(0);
    load_chunk(1);

    const uint32_t idesc = (1u << 4) | (1u << 7) | (1u << 10) |
                           ((TILE_N / 8) << 17) | ((TILE_M / 16) << 24);

    for (int c = 0; c < NCHUNK; c++) {
        const int buf = c & (NBUF - 1);
        // chunk c must be resident; at most one younger load group may be pending.
        if (c + 1 < NCHUNK) { CP_WAIT(1); } else { CP_WAIT(0); }
        FENCE_PROXY_ASYNC();
        __syncthreads();

        if (tid == 0) {
            const uint32_t base = sb + OFF_DATA + buf * SZ_BUF;
            const uint64_t dAH = make_desc_sw64(base);
            const uint64_t dAL = make_desc_sw64(base + SZ_A);
            const uint64_t dBH = make_desc_sw64(base + 2 * SZ_A);
            const uint64_t dBL = make_desc_sw64(base + 2 * SZ_A + SZ_B);
            #pragma unroll
            for (int ks = 0; ks < 2; ks++) {
                const uint64_t o = ks * 2;   // 16 bf16 = 32B = 2 x 16B units
                mma_bf16_ss(tmem, dAH + o, dBH + o, idesc, (c | ks) != 0);
                mma_bf16_ss(tmem, dAH + o, dBL + o, idesc, 1u);
                mma_bf16_ss(tmem, dAL + o, dBH + o, idesc, 1u);
            }
            TCGEN05_COMMIT(sb + OFF_MB + buf * 8);
        }

        // Prefetch chunk c+2. Its buffer last held chunk c-2: wait for that
        // chunk's MMAs (committed 2 iterations ago -> usually already done).
        if (c + 2 < NCHUNK) {
            const int cc = c - 2;   // chunk previously in buffer (c+2)&3
            if (cc >= 0) {
                MBARRIER_WAIT_PARITY(sb + OFF_MB + (cc & (NBUF - 1)) * 8,
                                     (uint32_t)((cc >> 2) & 1));
            }
            load_chunk(c + 2);
        }
    }

    // All MMAs issued in order; waiting on the final commit covers them all.
    {
        const int cl = NCHUNK - 1;
        MBARRIER_WAIT_PARITY(sb + OFF_MB + (cl & (NBUF - 1)) * 8,
                             (uint32_t)((cl >> 2) & 1));
    }
    TCGEN05_FENCE_AFTER();

    // -------- epilogue --------
    const int w    = tid >> 5, lane = tid & 31;
    const int part = w & 3,    half = w >> 2;
    const int row  = bm * TILE_M + part * 32 + lane;
    float* crow = C + (size_t)row * DDIM;

    #pragma unroll
    for (int batch = 0; batch < 4; batch++) {
        const int colbase = half * 128 + batch * 32;
        uint32_t r[32];
        TCGEN05_LD_X32(r, tmem + colbase);
        TCGEN05_WAIT_LD();
        const int gcol0 = bn * TILE_N + colbase;
        #pragma unroll
        for (int i = 0; i < 32; i += 4) {
            const float4 bv = __ldg((const float4*)(bias + gcol0 + i));
            float4 o;
            o.x = __uint_as_float(r[i + 0]) + bv.x;
            o.y = __uint_as_float(r[i + 1]) + bv.y;
            o.z = __uint_as_float(r[i + 2]) + bv.z;
            o.w = __uint_as_float(r[i + 3]) + bv.w;
            *(float4*)(crow + gcol0 + i) = o;
        }
    }

    __syncthreads();
    if (tid < 32) TCGEN05_DEALLOC(tmem, 256);
#endif // HAS_TCGEN05
}

// ======================= launch =======================
extern "C" void kernel_launch(void* const* d_in, const int* in_sizes, int n_in,
                              void* d_out, int out_size) {
    const int*   token_ids         = (const int*)  d_in[0];
    const int*   segment_ids       = (const int*)  d_in[1];
    const int*   section_ids       = (const int*)  d_in[2];
    const int*   temporality_ids   = (const int*)  d_in[3];
    const int*   negation_ids      = (const int*)  d_in[4];
    const int*   position_ids      = (const int*)  d_in[5];
    const int*   timestamp_ids     = (const int*)  d_in[6];
    const float* token_table       = (const float*)d_in[7];
    const float* section_table     = (const float*)d_in[8];
    const float* temporality_table = (const float*)d_in[9];
    const float* negation_table    = (const float*)d_in[10];
    const float* position_table    = (const float*)d_in[11];
    const float* timestamp_table   = (const float*)d_in[12];
    const float* ln_gamma          = (const float*)d_in[13];
    const float* ln_beta           = (const float*)d_in[14];
    const float* proj_w            = (const float*)d_in[15];
    const float* proj_b            = (const float*)d_in[16];

    float* out = (float*)d_out;

    cudaFuncSetAttribute(gemm_tc_kernel,
                         cudaFuncAttributeMaxDynamicSharedMemorySize, GEMM_SMEM);

    segstart_kernel<<<NTOK / 256, 256>>>(segment_ids);

    wsplit_kernel<<<(DDIM * DDIM / 4) / 256, 256>>>(proj_w);

    embed_ln_kernel<<<NSLOT, 192>>>(
        token_ids, section_ids, temporality_ids, negation_ids,
        position_ids, timestamp_ids, token_table, section_table,
        temporality_table, negation_table, position_table, timestamp_table,
        ln_gamma, ln_beta);

    dim3 grid_tc(DDIM / TILE_N, NSLOT / TILE_M);   // (3, 32)
    gemm_tc_kernel<<<grid_tc, 256, GEMM_SMEM>>>(proj_b, out,
                                                NSLOT * DDIM, out_size);
}